// round 7
// baseline (speedup 1.0000x reference)
#include <cuda_runtime.h>

#define CCH 512
#define TT  8192
#define MM  5
#define PLANE (TT * CCH)

// ---- static device scratch ----
__device__ float  g_U[TT * 16];       // U[t,j] = b1[j] + W1^T y_t
__device__ float  g_invd[TT];         // rsqrt(s_t)
__device__ float2 g_KV2[5 * PLANE];   // plane m, [t][c]: {K[t,c,m], V[t,c,m]}
__device__ float  g_dotT[PLANE];      // raw dot, t-major [t][c]

// ---------------- repack K,V into planar {k,v} float2 layout ----------------
__global__ void repack_kv(const float* __restrict__ K, const float* __restrict__ V)
{
    const int idx = blockIdx.x * blockDim.x + threadIdx.x;   // t*512 + c
    const long b = (long)idx * 5;
#pragma unroll
    for (int m = 0; m < MM; m++)
        g_KV2[m * PLANE + idx] = make_float2(K[b + m], V[b + m]);
}

// ---------------- precompute U (parallel) ----------------
__global__ void precompute_U(const float* __restrict__ y,
                             const float* __restrict__ W1,
                             const float* __restrict__ b1)
{
    const int j  = threadIdx.x & 15;
    const int t4 = blockIdx.x * 32 + (threadIdx.x >> 4);
    const int t0 = t4 * 4;
    const float bj = b1[j];
    float a0 = bj, a1 = bj, a2 = bj, a3 = bj;
#pragma unroll 8
    for (int c = 0; c < CCH; c++) {
        const float4 yv = *(const float4*)&y[c * TT + t0];
        const float w = W1[c * 16 + j];
        a0 = fmaf(yv.x, w, a0);
        a1 = fmaf(yv.y, w, a1);
        a2 = fmaf(yv.z, w, a2);
        a3 = fmaf(yv.w, w, a3);
    }
    g_U[(t0 + 0) * 16 + j] = a0;
    g_U[(t0 + 1) * 16 + j] = a1;
    g_U[(t0 + 2) * 16 + j] = a2;
    g_U[(t0 + 3) * 16 + j] = a3;
}

// ---------------- sequential recurrence, 1 CTA ----------------
// scratch layout: sgp[j][w] = scratch[18*j + w]  (pad 18 -> conflict-free)
//                 ssp[w]    = scratch[288 + w]
// Phase B: warp wid: lanes<16 read sgp[wid][lane], lanes>=16 read ssp[lane-16];
//          4-round half-warp butterfly; xor16 cross; inv=rsqrt(s); sh[wid]=relu(g*inv+U).
// Phase C: q[c] from sh (broadcast LDS) + W2 regs.
// Phase A: ema/dot/sp in regs; per-warp multi-value butterfly reduces
//          {dot*W1[c,j]}_j over the warp's 32 channels -> 16 partials -> sgp;
//          sp 5-round butterfly -> ssp;  coalesced STG of raw dot.
__global__ __launch_bounds__(512, 1)
void rca_kernel(const float* __restrict__ W1,
                const float* __restrict__ W2,
                const float* __restrict__ b2)
{
    __shared__ __align__(16) float sh[16];
    __shared__ float scratch[304];

    const int tid  = threadIdx.x;
    const int wid  = tid >> 5;
    const int lane = tid & 31;

    // weights in registers: thread owns channel c = tid
    float w1r[16], w2r[16];
#pragma unroll
    for (int j = 0; j < 16; j++) {
        w1r[j] = W1[tid * 16 + j];
        w2r[j] = W2[j * CCH + tid];
    }
    const float b2c = b2[tid];

    float e0 = 0.f, e1 = 0.f, e2 = 0.f, e3 = 0.f, e4 = 0.f;

    // depth-2 prefetch
    float2 kv[2][MM];
    float  ub[2];
#pragma unroll
    for (int i = 0; i < 2; i++) {
        const int idx = i * CCH + tid;
#pragma unroll
        for (int m = 0; m < MM; m++) kv[i][m] = g_KV2[m * PLANE + idx];
        ub[i] = g_U[i * 16 + wid];
    }

    if (tid < 304) scratch[tid] = 0.f;
    __syncthreads();

    for (int t0 = 0; t0 < TT + 2; t0 += 2) {
#pragma unroll
        for (int i = 0; i < 2; i++) {
            const int t = t0 + i;

            // ---------- B: second-level reduce -> h ----------
            float p = (lane < 16) ? scratch[18 * wid + lane]
                                  : scratch[288 + lane - 16];
            p += __shfl_xor_sync(0xffffffffu, p, 8);
            p += __shfl_xor_sync(0xffffffffu, p, 4);
            p += __shfl_xor_sync(0xffffffffu, p, 2);
            p += __shfl_xor_sync(0xffffffffu, p, 1);
            const float other = __shfl_xor_sync(0xffffffffu, p, 16);
            const float g = (lane < 16) ? p : other;
            const float s = (lane < 16) ? other : p;
            const float inv = rsqrtf(fmaxf(s, 1e-37f));
            if (lane == 0) {
                sh[wid] = fmaxf(fmaf(g, inv, ub[i]), 0.f);
                if (wid == 0 && t > 0) g_invd[t - 1] = inv;
            }
            if (t == TT) return;

            __syncthreads();   // sh visible; scratch reads done before A writes

            // ---------- C: q[c] = b2[c] + sum_j h[j]*W2[j,c] ----------
            const float4 h0 = *(const float4*)&sh[0];
            const float4 h1 = *(const float4*)&sh[4];
            const float4 h2 = *(const float4*)&sh[8];
            const float4 h3 = *(const float4*)&sh[12];
            float q0 = b2c, q1 = 0.f, q2 = 0.f, q3 = 0.f;
            q0 = fmaf(h0.x, w2r[0],  q0); q1 = fmaf(h0.y, w2r[1],  q1);
            q2 = fmaf(h0.z, w2r[2],  q2); q3 = fmaf(h0.w, w2r[3],  q3);
            q0 = fmaf(h1.x, w2r[4],  q0); q1 = fmaf(h1.y, w2r[5],  q1);
            q2 = fmaf(h1.z, w2r[6],  q2); q3 = fmaf(h1.w, w2r[7],  q3);
            q0 = fmaf(h2.x, w2r[8],  q0); q1 = fmaf(h2.y, w2r[9],  q1);
            q2 = fmaf(h2.z, w2r[10], q2); q3 = fmaf(h2.w, w2r[11], q3);
            q0 = fmaf(h3.x, w2r[12], q0); q1 = fmaf(h3.y, w2r[13], q1);
            q2 = fmaf(h3.z, w2r[14], q2); q3 = fmaf(h3.w, w2r[15], q3);
            const float qm = 0.05f * ((q0 + q1) + (q2 + q3));

            // ---------- A: ema update, dot, sp ----------
            e0 = fmaf(0.95f, e0, qm * kv[i][0].x);
            e1 = fmaf(0.95f, e1, qm * kv[i][1].x);
            e2 = fmaf(0.95f, e2, qm * kv[i][2].x);
            e3 = fmaf(0.95f, e3, qm * kv[i][3].x);
            e4 = fmaf(0.95f, e4, qm * kv[i][4].x);
            float dot = e0 * kv[i][0].y;
            dot = fmaf(e1, kv[i][1].y, dot);
            dot = fmaf(e2, kv[i][2].y, dot);
            dot = fmaf(e3, kv[i][3].y, dot);
            dot = fmaf(e4, kv[i][4].y, dot);
            float sp = e0 * e0;
            sp = fmaf(e1, e1, sp);
            sp = fmaf(e2, e2, sp);
            sp = fmaf(e3, e3, sp);
            sp = fmaf(e4, e4, sp);

            g_dotT[t * CCH + tid] = dot;   // coalesced raw store

            // prefetch t+2 into this slot
            {
                const int tn  = (t + 2 < TT) ? (t + 2) : (TT - 1);
                const int idx = tn * CCH + tid;
#pragma unroll
                for (int m = 0; m < MM; m++) kv[i][m] = g_KV2[m * PLANE + idx];
                ub[i] = g_U[tn * 16 + wid];
            }

            // ---------- W1 partials + multi-value butterfly ----------
            float v[16];
#pragma unroll
            for (int j = 0; j < 16; j++) v[j] = dot * w1r[j];

            {
                bool hi = (lane & 16) != 0;
#pragma unroll
                for (int ii = 0; ii < 8; ii++) {
                    const float keep = hi ? v[8 + ii] : v[ii];
                    const float send = hi ? v[ii] : v[8 + ii];
                    v[ii] = keep + __shfl_xor_sync(0xffffffffu, send, 16);
                }
                hi = (lane & 8) != 0;
#pragma unroll
                for (int ii = 0; ii < 4; ii++) {
                    const float keep = hi ? v[4 + ii] : v[ii];
                    const float send = hi ? v[ii] : v[4 + ii];
                    v[ii] = keep + __shfl_xor_sync(0xffffffffu, send, 8);
                }
                hi = (lane & 4) != 0;
#pragma unroll
                for (int ii = 0; ii < 2; ii++) {
                    const float keep = hi ? v[2 + ii] : v[ii];
                    const float send = hi ? v[ii] : v[2 + ii];
                    v[ii] = keep + __shfl_xor_sync(0xffffffffu, send, 4);
                }
                hi = (lane & 2) != 0;
                {
                    const float keep = hi ? v[1] : v[0];
                    const float send = hi ? v[0] : v[1];
                    v[0] = keep + __shfl_xor_sync(0xffffffffu, send, 2);
                }
                v[0] += __shfl_xor_sync(0xffffffffu, v[0], 1);
            }
            // lane (2j, 2j+1) both hold P[j]; even lanes store (conflict-free)
            // sp butterfly (pipelines with the above)
            sp += __shfl_xor_sync(0xffffffffu, sp, 16);
            sp += __shfl_xor_sync(0xffffffffu, sp, 8);
            sp += __shfl_xor_sync(0xffffffffu, sp, 4);
            sp += __shfl_xor_sync(0xffffffffu, sp, 2);
            sp += __shfl_xor_sync(0xffffffffu, sp, 1);

            if (!(lane & 1)) scratch[18 * ((lane >> 1) & 15) + wid] = v[0];
            if (lane == 1)   scratch[288 + wid] = sp;

            __syncthreads();   // scratch visible for next B
        }
    }
}

// ---------------- transpose + scale: out[c*TT+t] = dotT[t][c] * invd[t] ----------------
__global__ void transpose_scale(float* __restrict__ out)
{
    __shared__ float tile[32][33];
    const int t0 = blockIdx.x * 32;
    const int c0 = blockIdx.y * 32;
    const int tx = threadIdx.x;
    const int ty = threadIdx.y;

#pragma unroll
    for (int r = ty; r < 32; r += 8)
        tile[r][tx] = g_dotT[(t0 + r) * CCH + (c0 + tx)] * g_invd[t0 + r];
    __syncthreads();
#pragma unroll
    for (int r = ty; r < 32; r += 8)
        out[(long)(c0 + r) * TT + (t0 + tx)] = tile[tx][r];
}

extern "C" void kernel_launch(void* const* d_in, const int* in_sizes, int n_in,
                              void* d_out, int out_size) {
    const float* y  = (const float*)d_in[0];
    const float* Kp = (const float*)d_in[1];
    const float* Vp = (const float*)d_in[2];
    const float* W1 = (const float*)d_in[3];
    const float* b1 = (const float*)d_in[4];
    const float* W2 = (const float*)d_in[5];
    const float* b2 = (const float*)d_in[6];
    float* out = (float*)d_out;

    repack_kv<<<(TT * CCH) / 256, 256>>>(Kp, Vp);
    precompute_U<<<TT / 128, 512>>>(y, W1, b1);
    rca_kernel<<<1, 512>>>(W1, W2, b2);
    dim3 tb(32, 8);
    dim3 tg(TT / 32, CCH / 32);
    transpose_scale<<<tg, tb>>>(out);
}

// round 8
// speedup vs baseline: 1.1303x; 1.1303x over previous
#include <cuda_runtime.h>

#define CCH 512
#define TT  8192
#define MM  5
#define PLANE (TT * CCH)

typedef unsigned long long u64;

__device__ __forceinline__ u64 fma2(u64 a, u64 b, u64 c) {
    u64 d; asm("fma.rn.f32x2 %0, %1, %2, %3;" : "=l"(d) : "l"(a), "l"(b), "l"(c)); return d;
}
__device__ __forceinline__ u64 mul2(u64 a, u64 b) {
    u64 d; asm("mul.rn.f32x2 %0, %1, %2;" : "=l"(d) : "l"(a), "l"(b)); return d;
}
__device__ __forceinline__ u64 pack2(float lo, float hi) {
    u64 d; asm("mov.b64 %0, {%1, %2};" : "=l"(d) : "f"(lo), "f"(hi)); return d;
}
__device__ __forceinline__ float2 unpack2(u64 a) {
    float2 r; asm("mov.b64 {%0, %1}, %2;" : "=f"(r.x), "=f"(r.y) : "l"(a)); return r;
}

// ---- static device scratch ----
__device__ float g_U[TT * 16];        // U[t,j] = b1[j] + W1^T y_t
__device__ float g_invd[TT];          // rsqrt(s_t)
__device__ u64   g_KVu[5 * PLANE];    // plane 0:(k0,k1) 1:(k2,k3) 2:(v0,v1) 3:(v2,v3) 4:(k4,v4); [m][t][c]
__device__ float g_dotT[PLANE];       // raw dot, t-major [t][c]

// ---------------- repack K,V into paired planar layout ----------------
__global__ void repack_kv(const float* __restrict__ K, const float* __restrict__ V)
{
    const int idx = blockIdx.x * blockDim.x + threadIdx.x;   // t*512 + c
    const long b = (long)idx * 5;
    g_KVu[0 * PLANE + idx] = pack2(K[b + 0], K[b + 1]);
    g_KVu[1 * PLANE + idx] = pack2(K[b + 2], K[b + 3]);
    g_KVu[2 * PLANE + idx] = pack2(V[b + 0], V[b + 1]);
    g_KVu[3 * PLANE + idx] = pack2(V[b + 2], V[b + 3]);
    g_KVu[4 * PLANE + idx] = pack2(K[b + 4], V[b + 4]);
}

// ---------------- precompute U (parallel) ----------------
__global__ void precompute_U(const float* __restrict__ y,
                             const float* __restrict__ W1,
                             const float* __restrict__ b1)
{
    const int j  = threadIdx.x & 15;
    const int t4 = blockIdx.x * 32 + (threadIdx.x >> 4);
    const int t0 = t4 * 4;
    const float bj = b1[j];
    float a0 = bj, a1 = bj, a2 = bj, a3 = bj;
#pragma unroll 8
    for (int c = 0; c < CCH; c++) {
        const float4 yv = *(const float4*)&y[c * TT + t0];
        const float w = W1[c * 16 + j];
        a0 = fmaf(yv.x, w, a0);
        a1 = fmaf(yv.y, w, a1);
        a2 = fmaf(yv.z, w, a2);
        a3 = fmaf(yv.w, w, a3);
    }
    g_U[(t0 + 0) * 16 + j] = a0;
    g_U[(t0 + 1) * 16 + j] = a1;
    g_U[(t0 + 2) * 16 + j] = a2;
    g_U[(t0 + 3) * 16 + j] = a3;
}

// ---------------- sequential recurrence, 1 CTA (R6 structure) ----------------
__global__ __launch_bounds__(512, 1)
void rca_kernel(const float* __restrict__ W1,
                const float* __restrict__ W2,
                const float* __restrict__ b2)
{
    __shared__ float sdot[CCH];
    __shared__ float ss[16];
    __shared__ __align__(16) float sh[16];

    const int tid  = threadIdx.x;
    const int wid  = tid >> 5;
    const int lane = tid & 31;

    // B-phase channel mapping: lane handles c = 4*lane + 128*ii + k (conflict-free LDS.128)
    float w1r[16];
#pragma unroll
    for (int ii = 0; ii < 4; ii++)
#pragma unroll
        for (int k = 0; k < 4; k++)
            w1r[4 * ii + k] = W1[(4 * lane + 128 * ii + k) * 16 + wid];

    float w2r[16];
#pragma unroll
    for (int j = 0; j < 16; j++) w2r[j] = W2[j * CCH + tid];
    const float b2c = b2[tid];

    // packed EMA state: e01=(e0,e1), e23=(e2,e3), e4 scalar
    u64 e01 = pack2(0.f, 0.f), e23 = pack2(0.f, 0.f);
    float e4 = 0.f;
    const u64 c95 = pack2(0.95f, 0.95f);

    // depth-3 prefetch: 5 packed u64 per (t,c) + U
    u64  kv[3][5];
    float ub[3];
#pragma unroll
    for (int i = 0; i < 3; i++) {
        const int idx = i * CCH + tid;
#pragma unroll
        for (int m = 0; m < 5; m++) kv[i][m] = g_KVu[m * PLANE + idx];
        ub[i] = g_U[i * 16 + wid];
    }

    sdot[tid] = 0.f;
    if (tid < 16) ss[tid] = 0.f;
    __syncthreads();

    const float4* sd4 = (const float4*)sdot;

    for (int t0 = 0; t0 < TT + 3; t0 += 3) {
#pragma unroll
        for (int i = 0; i < 3; i++) {
            const int t = t0 + i;

            // ---------- B: g[wid] = sum_c dot_prev[c]*W1[c,wid]; s = sum ema^2 ----------
            float g0 = 0.f, g1 = 0.f, g2 = 0.f, g3 = 0.f;
#pragma unroll
            for (int ii = 0; ii < 4; ii++) {
                const float4 d = sd4[lane + 32 * ii];
                g0 = fmaf(d.x, w1r[4 * ii + 0], g0);
                g1 = fmaf(d.y, w1r[4 * ii + 1], g1);
                g2 = fmaf(d.z, w1r[4 * ii + 2], g2);
                g3 = fmaf(d.w, w1r[4 * ii + 3], g3);
            }
            float g = (g0 + g1) + (g2 + g3);
            float s = ss[lane & 15];
            // interleaved butterflies: g (5 rounds), s (4 rounds)
            g += __shfl_xor_sync(0xffffffffu, g, 16);
            s += __shfl_xor_sync(0xffffffffu, s, 8);
            g += __shfl_xor_sync(0xffffffffu, g, 8);
            s += __shfl_xor_sync(0xffffffffu, s, 4);
            g += __shfl_xor_sync(0xffffffffu, g, 4);
            s += __shfl_xor_sync(0xffffffffu, s, 2);
            g += __shfl_xor_sync(0xffffffffu, g, 2);
            s += __shfl_xor_sync(0xffffffffu, s, 1);
            g += __shfl_xor_sync(0xffffffffu, g, 1);

            const float inv = rsqrtf(fmaxf(s, 1e-37f));
            if (lane == 0) {
                sh[wid] = fmaxf(fmaf(g, inv, ub[i]), 0.f);
                if (wid == 0 && t > 0) g_invd[t - 1] = inv;
            }
            if (t == TT) return;

            __syncthreads();   // sh visible; ss/sdot reads done before A writes

            // ---------- C: q[c] = b2[c] + sum_j h[j]*W2[j,c] ----------
            const float4 h0 = *(const float4*)&sh[0];
            const float4 h1 = *(const float4*)&sh[4];
            const float4 h2 = *(const float4*)&sh[8];
            const float4 h3 = *(const float4*)&sh[12];
            float q0 = b2c, q1 = 0.f, q2 = 0.f, q3 = 0.f;
            q0 = fmaf(h0.x, w2r[0],  q0); q1 = fmaf(h0.y, w2r[1],  q1);
            q2 = fmaf(h0.z, w2r[2],  q2); q3 = fmaf(h0.w, w2r[3],  q3);
            q0 = fmaf(h1.x, w2r[4],  q0); q1 = fmaf(h1.y, w2r[5],  q1);
            q2 = fmaf(h1.z, w2r[6],  q2); q3 = fmaf(h1.w, w2r[7],  q3);
            q0 = fmaf(h2.x, w2r[8],  q0); q1 = fmaf(h2.y, w2r[9],  q1);
            q2 = fmaf(h2.z, w2r[10], q2); q3 = fmaf(h2.w, w2r[11], q3);
            q0 = fmaf(h3.x, w2r[12], q0); q1 = fmaf(h3.y, w2r[13], q1);
            q2 = fmaf(h3.z, w2r[14], q2); q3 = fmaf(h3.w, w2r[15], q3);
            const float qm = 0.05f * ((q0 + q1) + (q2 + q3));

            // ---------- A: packed ema update, dot, sp ----------
            const u64 qm2 = pack2(qm, qm);
            e01 = fma2(e01, c95, mul2(kv[i][0], qm2));
            e23 = fma2(e23, c95, mul2(kv[i][1], qm2));
            const float2 k4v4 = unpack2(kv[i][4]);
            e4 = fmaf(0.95f, e4, qm * k4v4.x);

            u64 d2 = mul2(e01, kv[i][2]);
            d2 = fma2(e23, kv[i][3], d2);
            const float2 dd = unpack2(d2);
            float dot = dd.x + dd.y;
            dot = fmaf(e4, k4v4.y, dot);

            u64 s2 = mul2(e01, e01);
            s2 = fma2(e23, e23, s2);
            const float2 sv = unpack2(s2);
            float sp = sv.x + sv.y;
            sp = fmaf(e4, e4, sp);

            sdot[tid] = dot;
            g_dotT[t * CCH + tid] = dot;   // coalesced raw store

            // prefetch t+3 into this slot
            {
                const int tn  = (t + 3 < TT) ? (t + 3) : (TT - 1);
                const int idx = tn * CCH + tid;
#pragma unroll
                for (int m = 0; m < 5; m++) kv[i][m] = g_KVu[m * PLANE + idx];
                ub[i] = g_U[tn * 16 + wid];
            }

            // warp-reduce sp -> ss[wid]
            sp += __shfl_xor_sync(0xffffffffu, sp, 16);
            sp += __shfl_xor_sync(0xffffffffu, sp, 8);
            sp += __shfl_xor_sync(0xffffffffu, sp, 4);
            sp += __shfl_xor_sync(0xffffffffu, sp, 2);
            sp += __shfl_xor_sync(0xffffffffu, sp, 1);
            if (lane == 0) ss[wid] = sp;

            __syncthreads();   // sdot/ss visible for next B
        }
    }
}

// ---------------- transpose + scale: out[c*TT+t] = dotT[t][c] * invd[t] ----------------
__global__ void transpose_scale(float* __restrict__ out)
{
    __shared__ float tile[32][33];
    const int t0 = blockIdx.x * 32;
    const int c0 = blockIdx.y * 32;
    const int tx = threadIdx.x;
    const int ty = threadIdx.y;

#pragma unroll
    for (int r = ty; r < 32; r += 8)
        tile[r][tx] = g_dotT[(t0 + r) * CCH + (c0 + tx)] * g_invd[t0 + r];
    __syncthreads();
#pragma unroll
    for (int r = ty; r < 32; r += 8)
        out[(long)(c0 + r) * TT + (t0 + tx)] = tile[tx][r];
}

extern "C" void kernel_launch(void* const* d_in, const int* in_sizes, int n_in,
                              void* d_out, int out_size) {
    const float* y  = (const float*)d_in[0];
    const float* Kp = (const float*)d_in[1];
    const float* Vp = (const float*)d_in[2];
    const float* W1 = (const float*)d_in[3];
    const float* b1 = (const float*)d_in[4];
    const float* W2 = (const float*)d_in[5];
    const float* b2 = (const float*)d_in[6];
    float* out = (float*)d_out;

    repack_kv<<<(TT * CCH) / 256, 256>>>(Kp, Vp);
    precompute_U<<<TT / 128, 512>>>(y, W1, b1);
    rca_kernel<<<1, 512>>>(W1, W2, b2);
    dim3 tb(32, 8);
    dim3 tg(TT / 32, CCH / 32);
    transpose_scale<<<tg, tb>>>(out);
}